// round 1
// baseline (speedup 1.0000x reference)
#include <cuda_runtime.h>

// Antialiased bilinear (triangle-filter) 4x downsample, separable 8-tap.
// x: (2048, 6, 128, 96) f32  ->  out: (2048, 6, 32, 24) f32 (flattened to (B,6,768))

#define IMGS    12288      // 2048 * 6
#define IN_H    128
#define IN_W    96
#define OUT_H   32
#define OUT_W   24
#define THREADS 256
#define IMG_SMEM_BYTES (IN_H * IN_W * 4)   // 48 KB dynamic

__global__ __launch_bounds__(THREADS)
void resize_aa_kernel(const float* __restrict__ x, float* __restrict__ out)
{
    extern __shared__ float img[];             // [IN_H][IN_W], 48 KB dynamic
    __shared__ float inter[IN_H][OUT_W];       // 12 KB
    __shared__ float wh[OUT_H][8];             // vertical weights
    __shared__ float ww[OUT_W][8];             // horizontal weights

    const int t = threadIdx.x;
    const size_t img_id = blockIdx.x;

    // ---- coalesced load of the whole (128x96) image: 3072 float4, 12/thread ----
    const float4* __restrict__ src = (const float4*)(x + img_id * (size_t)(IN_H * IN_W));
    float4* dst = (float4*)img;
#pragma unroll
    for (int k = 0; k < (IN_H * IN_W / 4) / THREADS; ++k)
        dst[t + k * THREADS] = src[t + k * THREADS];

    // ---- normalized 8-tap triangle weights (scale 1/4, center 4i+1.5) ----
    // tap j = 4i-2+k, k=0..7; unnormalized w = 1 - |k-3.5|/4; out-of-range taps
    // dropped, remaining renormalized to sum 1 (matches jax antialias resize).
    if (t < OUT_H + OUT_W) {
        const bool isH = (t < OUT_H);
        const int  i   = isH ? t : t - OUT_H;
        const int  IN  = isH ? IN_H : IN_W;
        float* wrow    = isH ? wh[i] : ww[i];
        float wtmp[8];
        float s = 0.f;
#pragma unroll
        for (int k = 0; k < 8; ++k) {
            const int j = 4 * i - 2 + k;
            float w = 1.f - fabsf((float)k - 3.5f) * 0.25f;
            if (j < 0 || j >= IN) w = 0.f;
            wtmp[k] = w;
            s += w;
        }
        const float inv = 1.f / s;
#pragma unroll
        for (int k = 0; k < 8; ++k) wrow[k] = wtmp[k] * inv;
    }
    __syncthreads();

    // ---- horizontal pass: 128 rows x 24 out-cols = 3072 elems, 12/thread ----
#pragma unroll
    for (int k = 0; k < (IN_H * OUT_W) / THREADS; ++k) {
        const int idx = t + k * THREADS;
        const int r  = idx / OUT_W;
        const int oc = idx % OUT_W;
        const float* __restrict__ row = img + r * IN_W;
        const int j0 = 4 * oc - 2;
        float acc = 0.f;
#pragma unroll
        for (int m = 0; m < 8; ++m) {
            int j = j0 + m;
            j = j < 0 ? 0 : (j >= IN_W ? IN_W - 1 : j);   // weight is 0 there anyway
            acc = fmaf(row[j], ww[oc][m], acc);
        }
        inter[r][oc] = acc;
    }
    __syncthreads();

    // ---- vertical pass: 32 x 24 = 768 outputs, 3/thread, coalesced store ----
    float* __restrict__ o = out + img_id * (size_t)(OUT_H * OUT_W);
#pragma unroll
    for (int k = 0; k < (OUT_H * OUT_W) / THREADS; ++k) {
        const int idx  = t + k * THREADS;
        const int orow = idx / OUT_W;
        const int oc   = idx % OUT_W;
        const int r0   = 4 * orow - 2;
        float acc = 0.f;
#pragma unroll
        for (int m = 0; m < 8; ++m) {
            int r = r0 + m;
            r = r < 0 ? 0 : (r >= IN_H ? IN_H - 1 : r);
            acc = fmaf(inter[r][oc], wh[orow][m], acc);
        }
        o[idx] = acc;
    }
}

extern "C" void kernel_launch(void* const* d_in, const int* in_sizes, int n_in,
                              void* d_out, int out_size)
{
    const float* x = (const float*)d_in[0];   // (2048,6,128,96) f32; d_in[1] (y) unused
    float* out = (float*)d_out;               // (2048,6,768) f32

    // Opt in to 48KB dynamic smem on top of ~14KB static. Idempotent, not a
    // stream op, safe under graph capture.
    cudaFuncSetAttribute(resize_aa_kernel,
                         cudaFuncAttributeMaxDynamicSharedMemorySize,
                         IMG_SMEM_BYTES);

    resize_aa_kernel<<<IMGS, THREADS, IMG_SMEM_BYTES>>>(x, out);
}

// round 2
// speedup vs baseline: 1.6056x; 1.6056x over previous
#include <cuda_runtime.h>

// Antialiased bilinear (triangle) 4x downsample, fully in registers + shuffles.
// x: (2048,6,128,96) f32 -> out: (2048,6,32,24) f32 (= (B,6,768))
//
// Layout: 1 block = 1 image (12288 blocks), 8 warps/block.
// Warp w owns output rows 4w..4w+3; it loads the 20 input rows they need
// (4*or0-2 .. 4*or0+17, clamped), lane oc<24 holds float4 = cols 4oc..4oc+3.
// Horizontal 8-tap (stride 4) per lane via 4 shuffles + 8 FMAs; vertical
// 8-tap entirely in registers. OOB taps get weight 0 + renormalize
// (matches jax.image.resize antialias).

#define IN_H  128
#define IN_W  96
#define OUT_H 32
#define OUT_W 24
#define IMGS  12288

__global__ __launch_bounds__(256)
void resize_aa_kernel(const float* __restrict__ x, float* __restrict__ out)
{
    const int lane = threadIdx.x & 31;
    const int warp = threadIdx.x >> 5;          // 0..7
    const size_t img = blockIdx.x;
    const bool act = lane < OUT_W;

    // ---- per-lane horizontal weights (8 taps at j = 4*lane-2+k), normalized ----
    float wh[8];
    {
        float s = 0.f;
#pragma unroll
        for (int k = 0; k < 8; ++k) {
            const int j = 4 * lane - 2 + k;
            float w = 1.f - fabsf((float)k - 3.5f) * 0.25f;   // triangle, scale 4
            w = (j >= 0 && j < IN_W) ? w : 0.f;
            wh[k] = w;
            s += w;
        }
        const float inv = (s > 0.f) ? (1.f / s) : 0.f;        // lanes >=25 have s==0
#pragma unroll
        for (int k = 0; k < 8; ++k) wh[k] *= inv;
    }

    const int or0   = warp * 4;                 // first output row of this warp
    const int rbase = 4 * or0 - 2;              // first input row needed

    const float* __restrict__ ip = x + img * (size_t)(IN_H * IN_W);

    // ---- load 20 rows, horizontal-filter each into h[i] ----
    float h[20];
#pragma unroll
    for (int i = 0; i < 20; ++i) {
        int r = rbase + i;
        r = r < 0 ? 0 : (r > IN_H - 1 ? IN_H - 1 : r);        // clamp (weight 0 anyway)
        float4 v = make_float4(0.f, 0.f, 0.f, 0.f);
        if (act) v = ((const float4*)(ip + (size_t)r * IN_W))[lane];

        const float pz = __shfl_up_sync(0xffffffffu, v.z, 1);   // col 4oc-2
        const float pw = __shfl_up_sync(0xffffffffu, v.w, 1);   // col 4oc-1
        const float nx = __shfl_down_sync(0xffffffffu, v.x, 1); // col 4oc+4
        const float ny = __shfl_down_sync(0xffffffffu, v.y, 1); // col 4oc+5

        float a;
        a = pz * wh[0];
        a = fmaf(pw,  wh[1], a);
        a = fmaf(v.x, wh[2], a);
        a = fmaf(v.y, wh[3], a);
        a = fmaf(v.z, wh[4], a);
        a = fmaf(v.w, wh[5], a);
        a = fmaf(nx,  wh[6], a);
        a = fmaf(ny,  wh[7], a);
        h[i] = a;
    }

    // ---- vertical 8-tap per output row, all in registers ----
    float* __restrict__ op = out + img * (size_t)(OUT_H * OUT_W);
#pragma unroll
    for (int o = 0; o < 4; ++o) {
        const int orow = or0 + o;
        float acc = 0.f, s = 0.f;
#pragma unroll
        for (int k = 0; k < 8; ++k) {
            const int r = 4 * orow - 2 + k;
            float w = 1.f - fabsf((float)k - 3.5f) * 0.25f;
            w = (r >= 0 && r < IN_H) ? w : 0.f;               // compile-time resolvable
            s += w;
            acc = fmaf(h[4 * o + k], w, acc);
        }
        if (act) op[orow * OUT_W + lane] = acc / s;           // renormalize edges
    }
}

extern "C" void kernel_launch(void* const* d_in, const int* in_sizes, int n_in,
                              void* d_out, int out_size)
{
    const float* x = (const float*)d_in[0];   // (2048,6,128,96) f32; d_in[1] unused
    float* out = (float*)d_out;               // (2048,6,768) f32
    resize_aa_kernel<<<IMGS, 256>>>(x, out);
}

// round 4
// speedup vs baseline: 1.8059x; 1.1248x over previous
#include <cuda_runtime.h>

// Antialiased bilinear (triangle) 4x downsample. Register-only, shuffle-based.
// x: (2048,6,128,96) f32 -> out: (2048,6,32,24) f32 (= (B,6,768))
//
// Mapping: block = 8 warps = HALF an image (16 output rows); grid = 24576.
// Warp w owns output rows or0=half*16+2w and or0+1 -> needs input rows
// 4*or0-2 .. 4*or0+9 (12 rows). All 12 row-loads (float4 per lane, lane<24)
// are hoisted into registers BEFORE any compute to maximize outstanding LDGs
// (MLP), then horizontal 8-tap via 4 shuffles + 8 FMAs per row, accumulated
// directly into the 2 vertical accumulators. OOB taps get weight 0 and the
// remaining weights renormalize (matches jax.image.resize antialias).

#define IN_H  128
#define IN_W  96
#define OUT_H 32
#define OUT_W 24
#define BLOCKS (12288 * 2)

__device__ __forceinline__ float tri8(int k) {        // unnormalized triangle tap
    return 1.f - fabsf((float)k - 3.5f) * 0.25f;
}

__global__ __launch_bounds__(256, 3)
void resize_aa_kernel(const float* __restrict__ x, float* __restrict__ out)
{
    const int lane = threadIdx.x & 31;
    const int warp = threadIdx.x >> 5;              // 0..7
    const size_t img  = blockIdx.x >> 1;
    const int   half  = blockIdx.x & 1;
    const bool  act   = lane < OUT_W;

    // ---- per-lane horizontal weights (taps j = 4*lane-2+k), normalized ----
    float wh[8];
    {
        float s = 0.f;
#pragma unroll
        for (int k = 0; k < 8; ++k) {
            const int j = 4 * lane - 2 + k;
            float w = tri8(k);
            w = (j >= 0 && j < IN_W) ? w : 0.f;
            wh[k] = w; s += w;
        }
        const float inv = (s > 0.f) ? (1.f / s) : 0.f;
#pragma unroll
        for (int k = 0; k < 8; ++k) wh[k] *= inv;
    }

    const int or0   = half * 16 + 2 * warp;         // first of 2 output rows
    const int rbase = 4 * or0 - 2;                  // first input row needed

    const float* __restrict__ ip = x + img * (size_t)(IN_H * IN_W);

    // ---- PHASE 1: hoist all 12 row loads (independent LDG.128s) ----
    float4 v[12];
#pragma unroll
    for (int i = 0; i < 12; ++i) {
        int r = rbase + i;
        r = r < 0 ? 0 : (r > IN_H - 1 ? IN_H - 1 : r);     // clamp; weight 0 there
        v[i] = act ? ((const float4*)(ip + (size_t)r * IN_W))[lane]
                   : make_float4(0.f, 0.f, 0.f, 0.f);
    }

    // ---- PHASE 2: horizontal filter each row, accumulate vertically ----
    float acc0 = 0.f, acc1 = 0.f;
#pragma unroll
    for (int i = 0; i < 12; ++i) {
        const float pz = __shfl_up_sync(0xffffffffu, v[i].z, 1);   // col 4oc-2
        const float pw = __shfl_up_sync(0xffffffffu, v[i].w, 1);   // col 4oc-1
        const float nx = __shfl_down_sync(0xffffffffu, v[i].x, 1); // col 4oc+4
        const float ny = __shfl_down_sync(0xffffffffu, v[i].y, 1); // col 4oc+5

        float h;
        h = pz * wh[0];
        h = fmaf(pw,     wh[1], h);
        h = fmaf(v[i].x, wh[2], h);
        h = fmaf(v[i].y, wh[3], h);
        h = fmaf(v[i].z, wh[4], h);
        h = fmaf(v[i].w, wh[5], h);
        h = fmaf(nx,     wh[6], h);
        h = fmaf(ny,     wh[7], h);

        // vertical taps: row i serves output row or0 with k=i (i<8),
        // and or0+1 with k=i-4 (i>=4). OOB rows contribute weight 0.
        if (i < 8) {
            const int r = rbase + i;
            const float w = (r >= 0 && r < IN_H) ? tri8(i) : 0.f;  // compile-time-ish
            acc0 = fmaf(h, w, acc0);
        }
        if (i >= 4) {
            const int r = rbase + i;
            const float w = (r >= 0 && r < IN_H) ? tri8(i - 4) : 0.f;
            acc1 = fmaf(h, w, acc1);
        }
    }

    // ---- vertical normalization (edge rows renormalize) + store ----
    float s0 = 0.f, s1 = 0.f;
#pragma unroll
    for (int k = 0; k < 8; ++k) {
        const int ra = 4 * or0 - 2 + k;
        const int rb = ra + 4;
        s0 += (ra >= 0 && ra < IN_H) ? tri8(k) : 0.f;
        s1 += (rb >= 0 && rb < IN_H) ? tri8(k) : 0.f;
    }

    float* __restrict__ op = out + img * (size_t)(OUT_H * OUT_W);
    if (act) {
        op[(or0)     * OUT_W + lane] = acc0 / s0;
        op[(or0 + 1) * OUT_W + lane] = acc1 / s1;
    }
}

extern "C" void kernel_launch(void* const* d_in, const int* in_sizes, int n_in,
                              void* d_out, int out_size)
{
    const float* x = (const float*)d_in[0];   // (2048,6,128,96) f32; d_in[1] unused
    float* out = (float*)d_out;               // (2048,6,768) f32
    resize_aa_kernel<<<BLOCKS, 256>>>(x, out);
}

// round 6
// speedup vs baseline: 2.0993x; 1.1625x over previous
#include <cuda_runtime.h>

// Antialiased bilinear (triangle) 4x downsample. Register-only, shuffle-based,
// constant-weight FFMA-imm, 64-reg diet for 4 CTAs/SM.
// x: (2048,6,128,96) f32 -> out: (2048,6,32,24) f32 (= (B,6,768))
//
// Mapping: block = 8 warps = HALF an image; warp owns output rows or0, or0+1,
// loads input rows 4*or0-2 .. 4*or0+9 (12 x LDG.128, lane<24 = 24 float4/row),
// all hoisted before compute. Horizontal 8-tap via 4 shuffles + FFMA with
// immediate weights (raw triangle taps .125/.375/.625/.875), then h *= inv_s
// where inv_s = 1/4 interior, 1/3.5 for edge lanes (OOB taps dropped +
// renormalized, matching jax.image.resize antialias). Vertical 8-tap with
// immediate weights; top/bottom output rows get exact edge correction.

#define IN_H  128
#define IN_W  96
#define OUT_H 32
#define OUT_W 24
#define BLOCKS (12288 * 2)

__global__ __launch_bounds__(256, 4)
void resize_aa_kernel(const float* __restrict__ x, float* __restrict__ out)
{
    const int lane = threadIdx.x & 31;
    const int warp = threadIdx.x >> 5;              // 0..7
    const size_t img  = blockIdx.x >> 1;
    const int   half  = blockIdx.x & 1;
    const bool  act   = lane < OUT_W;

    // per-lane horizontal edge handling (only lanes 0 and 23 are special)
    const float w0m   = (lane == 0)  ? 0.f : 0.125f;   // tap k=0 (zeroed: shfl_up garbage)
    const float w1m   = (lane == 0)  ? 0.f : 0.375f;   // tap k=1
    const float inv_s = (lane == 0 || lane == OUT_W - 1) ? (1.f / 3.5f) : 0.25f;

    const int or0   = half * 16 + 2 * warp;         // first of 2 output rows
    const int rbase = 4 * or0 - 2;                  // first input row needed

    const float* __restrict__ ip = x + img * (size_t)(IN_H * IN_W);

    // ---- PHASE 1: hoist all 12 row loads (independent LDG.128s) ----
    float4 v[12];
#pragma unroll
    for (int i = 0; i < 12; ++i) {
        int r = rbase + i;
        r = r < 0 ? 0 : (r > IN_H - 1 ? IN_H - 1 : r);   // clamp (corrected later)
        v[i] = act ? ((const float4*)(ip + (size_t)r * IN_W))[lane]
                   : make_float4(0.f, 0.f, 0.f, 0.f);    // lanes>=24 feed 0 to shfl_down
    }

    // ---- PHASE 2: horizontal filter + vertical accumulation ----
    // vertical raw taps: tri(k) = {.125,.375,.625,.875,.875,.625,.375,.125}
    float acc0 = 0.f, acc1 = 0.f;
    float h0 = 0.f, h1 = 0.f, h10 = 0.f, h11 = 0.f;     // kept for edge correction
#pragma unroll
    for (int i = 0; i < 12; ++i) {
        const float pz = __shfl_up_sync(0xffffffffu, v[i].z, 1);   // col 4oc-2
        const float pw = __shfl_up_sync(0xffffffffu, v[i].w, 1);   // col 4oc-1
        const float nx = __shfl_down_sync(0xffffffffu, v[i].x, 1); // col 4oc+4
        const float ny = __shfl_down_sync(0xffffffffu, v[i].y, 1); // col 4oc+5

        float h;
        h = pz * w0m;                       // masked on lane 0
        h = fmaf(pw,     w1m,    h);        // masked on lane 0
        h = fmaf(v[i].x, 0.625f, h);        // FFMA-imm from here on
        h = fmaf(v[i].y, 0.875f, h);
        h = fmaf(v[i].z, 0.875f, h);
        h = fmaf(v[i].w, 0.625f, h);
        h = fmaf(nx,     0.375f, h);        // lane 23: nx,ny are 0 (lane 24 holds 0)
        h = fmaf(ny,     0.125f, h);
        h *= inv_s;                         // per-lane renorm (edge lanes 1/3.5)

        // vertical: acc0 uses i=0..7 w/ tri(i); acc1 uses i=4..11 w/ tri(i-4)
        if (i < 8) {
            const float wv = 1.f - fabsf((float)i - 3.5f) * 0.25f;        // constant
            acc0 = fmaf(h, wv, acc0);
            if (i == 0) h0 = h;
            if (i == 1) h1 = h;
        }
        if (i >= 4) {
            const float wv = 1.f - fabsf((float)(i - 4) - 3.5f) * 0.25f;  // constant
            acc1 = fmaf(h, wv, acc1);
            if (i == 10) h10 = h;
            if (i == 11) h11 = h;
        }
    }

    // ---- vertical edge correction (uniform per warp, exact) ----
    // top image edge: or0==0 -> rows -2,-1 invalid for acc0 (they were clamps of row 0)
    if (or0 == 0)
        acc0 = (acc0 - h0 * 0.125f - h1 * 0.375f) * (1.f / 3.5f);
    else
        acc0 *= 0.25f;
    // bottom image edge: or0+1==31 -> rows 128,129 invalid for acc1
    if (or0 + 1 == OUT_H - 1)
        acc1 = (acc1 - h10 * 0.375f - h11 * 0.125f) * (1.f / 3.5f);
    else
        acc1 *= 0.25f;

    float* __restrict__ op = out + img * (size_t)(OUT_H * OUT_W);
    if (act) {
        op[(or0)     * OUT_W + lane] = acc0;
        op[(or0 + 1) * OUT_W + lane] = acc1;
    }
}

extern "C" void kernel_launch(void* const* d_in, const int* in_sizes, int n_in,
                              void* d_out, int out_size)
{
    const float* x = (const float*)d_in[0];   // (2048,6,128,96) f32; d_in[1] unused
    float* out = (float*)d_out;               // (2048,6,768) f32
    resize_aa_kernel<<<BLOCKS, 256>>>(x, out);
}

// round 7
// speedup vs baseline: 2.1977x; 1.0468x over previous
#include <cuda_runtime.h>

// Antialiased bilinear (triangle) 4x downsample. Register-only.
// x: (2048,6,128,96) f32 -> out: (2048,6,32,24) f32 (= (B,6,768))
//
// Block = 8 warps = HALF an image; warp owns output rows or0, or0+1, hoists
// its 12 input rows (LDG.128, lane<24) before compute. Horizontal 8-tap via
// partial-sum exchange: each lane sends 2-tap partials to its neighbors
// (2 shuffles/row instead of 4). Per-lane renorm (inv_s) and vertical norm
// are applied once at the end. OOB taps dropped + renormalized == jax
// antialias resize semantics.

#define IN_H  128
#define IN_W  96
#define OUT_H 32
#define OUT_W 24
#define BLOCKS (12288 * 2)

__global__ __launch_bounds__(256, 4)
void resize_aa_kernel(const float* __restrict__ x, float* __restrict__ out)
{
    const int lane = threadIdx.x & 31;
    const int warp = threadIdx.x >> 5;              // 0..7
    const size_t img  = blockIdx.x >> 1;
    const int   half  = blockIdx.x & 1;
    const bool  act   = lane < OUT_W;

    // per-lane constants: lane-0 mask for the up-shuffle, horizontal renorm
    const float m0    = (lane == 0) ? 0.f : 1.f;
    const float inv_s = (lane == 0 || lane == OUT_W - 1) ? (1.f / 3.5f) : 0.25f;

    const int or0   = half * 16 + 2 * warp;         // first of 2 output rows
    const int rbase = 4 * or0 - 2;                  // first input row needed

    const float* __restrict__ ip = x + img * (size_t)(IN_H * IN_W);

    // ---- PHASE 1: hoist all 12 row loads (independent LDG.128s) ----
    float4 v[12];
#pragma unroll
    for (int i = 0; i < 12; ++i) {
        int r = rbase + i;
        r = r < 0 ? 0 : (r > IN_H - 1 ? IN_H - 1 : r);   // clamp (corrected later)
        v[i] = act ? ((const float4*)(ip + (size_t)r * IN_W))[lane]
                   : make_float4(0.f, 0.f, 0.f, 0.f);    // lanes>=24 feed 0 downward
    }

    // ---- PHASE 2: horizontal filter (partial-sum exchange) + vertical acc ----
    // Output oc raw taps over cols 4oc-2..4oc+5: .125 .375 .625 .875 .875 .625 .375 .125
    //   own cols (x,y,z,w): .625 .875 .875 .625
    //   from lane-1 (its z,w): .125 .375   -> lane-1 computes pR, shfl_up
    //   from lane+1 (its x,y): .375 .125   -> lane+1 computes pL, shfl_down
    float acc0 = 0.f, acc1 = 0.f;
    float h0 = 0.f, h1 = 0.f, h10 = 0.f, h11 = 0.f;     // raw h for edge correction
#pragma unroll
    for (int i = 0; i < 12; ++i) {
        float pR = v[i].z * 0.125f; pR = fmaf(v[i].w, 0.375f, pR);  // -> lane+1
        float pL = v[i].x * 0.375f; pL = fmaf(v[i].y, 0.125f, pL);  // -> lane-1

        const float rcvU = __shfl_up_sync(0xffffffffu, pR, 1);   // from lane-1
        const float rcvD = __shfl_down_sync(0xffffffffu, pL, 1); // from lane+1 (0 at 23)

        float h;
        h = v[i].x * 0.625f;
        h = fmaf(v[i].y, 0.875f, h);
        h = fmaf(v[i].z, 0.875f, h);
        h = fmaf(v[i].w, 0.625f, h);
        h += rcvD;
        h = fmaf(rcvU, m0, h);              // lane-0 up-shuffle garbage masked

        // vertical raw taps tri(k) = {.125,.375,.625,.875,.875,.625,.375,.125}
        if (i < 8) {
            const float wv = 1.f - fabsf((float)i - 3.5f) * 0.25f;        // imm
            acc0 = fmaf(h, wv, acc0);
            if (i == 0) h0 = h;
            if (i == 1) h1 = h;
        }
        if (i >= 4) {
            const float wv = 1.f - fabsf((float)(i - 4) - 3.5f) * 0.25f;  // imm
            acc1 = fmaf(h, wv, acc1);
            if (i == 10) h10 = h;
            if (i == 11) h11 = h;
        }
    }

    // ---- vertical edge correction (exact, uniform per warp) + final norm ----
    if (or0 == 0)                           // rows -2,-1 were clamped dupes of row 0
        acc0 = (acc0 - h0 * 0.125f - h1 * 0.375f) * (1.f / 3.5f);
    else
        acc0 *= 0.25f;
    if (or0 + 1 == OUT_H - 1)               // rows 128,129 were clamped dupes of 127
        acc1 = (acc1 - h10 * 0.375f - h11 * 0.125f) * (1.f / 3.5f);
    else
        acc1 *= 0.25f;

    float* __restrict__ op = out + img * (size_t)(OUT_H * OUT_W);
    if (act) {
        op[(or0)     * OUT_W + lane] = acc0 * inv_s;
        op[(or0 + 1) * OUT_W + lane] = acc1 * inv_s;
    }
}

extern "C" void kernel_launch(void* const* d_in, const int* in_sizes, int n_in,
                              void* d_out, int out_size)
{
    const float* x = (const float*)d_in[0];   // (2048,6,128,96) f32; d_in[1] unused
    float* out = (float*)d_out;               // (2048,6,768) f32
    resize_aa_kernel<<<BLOCKS, 256>>>(x, out);
}